// round 9
// baseline (speedup 1.0000x reference)
#include <cuda_runtime.h>
#include <cuda_fp16.h>
#include <cstdint>

// ---------------- problem constants ----------------
#define BSZ    64
#define INSZ   8192
#define OUTSZ  8192
#define NGRP   128               // IN / 64
#define TILE_M 128               // output rows per CTA
#define KC     64                // K per chunk = one quant group
#define KSPLIT 4
#define KPER   (INSZ / KSPLIT)   // 2048
#define NCHUNK (KPER / KC)       // 32
#define NTHREADS 256

// padded-row SMEM: 64 k-halves = 128 bytes data + 16 pad = 144 B stride
#define ASTRIDE 144
#define SM_A0  0
#define SM_A1  18432             // 128 * 144
#define SM_X0  36864
#define SM_X1  46080             // + 64 * 144
#define SM_TOTAL 55296

#define WBYTES (OUTSZ * (INSZ / 4))      // 16,777,216 packed weight bytes
#define WWORDS (WBYTES / 4)              // 4,194,304

// ---------------- device scratch ----------------
__device__ __half  g_xh[BSZ * INSZ];              // x in fp16
__device__ uint2   g_lut[OUTSZ * NGRP];           // packed fp16 dequant LUT per (row,group)
__device__ float   g_part[KSPLIT * BSZ * OUTSZ];  // split-K partials
__device__ uint8_t g_wb[WBYTES];                  // canonical packed 2-bit weights
__device__ int     g_wfmt;                        // 0=uint8, 1=int32-widened, 2=float32-widened

// ---------------- helpers ----------------
__device__ __forceinline__ uint32_t smem_u32(const void* p) {
    uint32_t a;
    asm("{ .reg .u64 t; cvta.to.shared.u64 t, %1; cvt.u32.u64 %0, t; }" : "=r"(a) : "l"(p));
    return a;
}
__device__ __forceinline__ uint32_t lds32(uint32_t addr) {
    uint32_t v;
    asm volatile("ld.shared.b32 %0, [%1];" : "=r"(v) : "r"(addr));
    return v;
}
__device__ __forceinline__ void sts128(uint32_t addr, uint32_t r0, uint32_t r1,
                                       uint32_t r2, uint32_t r3) {
    asm volatile("st.shared.v4.b32 [%0], {%1, %2, %3, %4};"
                 :: "r"(addr), "r"(r0), "r"(r1), "r"(r2), "r"(r3) : "memory");
}
__device__ __forceinline__ void mma16816(float& c0, float& c1, float& c2, float& c3,
                                         uint32_t a0, uint32_t a1, uint32_t a2, uint32_t a3,
                                         uint32_t b0, uint32_t b1) {
    asm volatile("mma.sync.aligned.m16n8k16.row.col.f32.f16.f16.f32 "
                 "{%0,%1,%2,%3}, {%4,%5,%6,%7}, {%8,%9}, {%0,%1,%2,%3};"
                 : "+f"(c0), "+f"(c1), "+f"(c2), "+f"(c3)
                 : "r"(a0), "r"(a1), "r"(a2), "r"(a3), "r"(b0), "r"(b1));
}

// ---------------- probe: classify w_packed marshalling format ----------------
__global__ void probe_kernel(const uint32_t* __restrict__ w) {
    __shared__ int cnt_zero, cnt_float;
    if (threadIdx.x == 0) { cnt_zero = 0; cnt_float = 0; }
    __syncthreads();
    int lz = 0, lf = 0;
    for (int i = threadIdx.x; i < 4096; i += blockDim.x) {
        uint32_t tb = w[i] >> 24;
        if (tb == 0) lz++;
        if (tb == 0 || (tb >= 0x3Bu && tb <= 0x43u)) lf++;   // float encodings of 0..255
    }
    atomicAdd(&cnt_zero, lz);
    atomicAdd(&cnt_float, lf);
    __syncthreads();
    if (threadIdx.x == 0) {
        int fmt = 0;                       // packed uint8 (top bytes ~uniform)
        if (cnt_zero == 4096)      fmt = 1; // int32-widened (top byte always 0)
        else if (cnt_float >= 4000) fmt = 2; // float32-widened
        g_wfmt = fmt;
    }
}

// ---------------- repack: canonicalize w into packed uint8 g_wb ----------------
__global__ void repack_kernel(const void* __restrict__ w) {
    const int i = blockIdx.x * blockDim.x + threadIdx.x;   // output uint32 index
    if (i >= WWORDS) return;
    const int fmt = g_wfmt;
    uint32_t o;
    if (fmt == 1) {
        const uint4 v = ((const uint4*)w)[i];              // 4 widened ints
        o = (v.x & 0xFFu) | ((v.y & 0xFFu) << 8) | ((v.z & 0xFFu) << 16) | ((v.w & 0xFFu) << 24);
    } else if (fmt == 2) {
        const float4 v = ((const float4*)w)[i];            // 4 widened floats
        o = ((uint32_t)v.x) | (((uint32_t)v.y) << 8)
          | (((uint32_t)v.z) << 16) | (((uint32_t)v.w) << 24);
    } else {
        o = ((const uint32_t*)w)[i];                       // already packed: copy
    }
    ((uint32_t*)g_wb)[i] = o;
}

// ---------------- prep: x -> fp16, (scale,zp) -> packed fp16 LUT ----------------
__global__ void prep_kernel(const float* __restrict__ x,
                            const float* __restrict__ scales,
                            const int*   __restrict__ zps) {
    int idx = blockIdx.x * blockDim.x + threadIdx.x;   // 0 .. OUTSZ*NGRP-1
    if (idx < OUTSZ * NGRP) {
        float s = scales[idx];
        int   z = zps[idx];
        __half e0 = __float2half((float)(0 - z) * s);
        __half e1 = __float2half((float)(1 - z) * s);
        __half e2 = __float2half((float)(2 - z) * s);
        __half e3 = __float2half((float)(3 - z) * s);
        uint2 l;
        l.x = (uint32_t)__half_as_ushort(e0) | ((uint32_t)__half_as_ushort(e1) << 16);
        l.y = (uint32_t)__half_as_ushort(e2) | ((uint32_t)__half_as_ushort(e3) << 16);
        g_lut[idx] = l;
    }
    if (idx < BSZ * INSZ) {
        g_xh[idx] = __float2half(x[idx]);
    }
}

// ---------------- main: fused dequant + mma.sync fp16 GEMM ----------------
__global__ void __launch_bounds__(NTHREADS, 1)
main_kernel() {
    extern __shared__ char smem[];
    const uint32_t sb  = smem_u32(smem);
    const int tid = threadIdx.x;
    const int wid = tid >> 5;
    const int lid = tid & 31;

    const int ot    = blockIdx.x / KSPLIT;      // OUT tile
    const int ks    = blockIdx.x % KSPLIT;      // K split
    const int o0    = ot * TILE_M;
    const int kbase = ks * KPER;

    // warp tiling: 4 (m) x 2 (n) warps; warp tile = 32 out-rows x 32 batch-cols
    const int wm = wid >> 1;
    const int wn = wid & 1;

    // ---- dequant mapping: 2 threads per A row, 32 halves each ----
    const int r    = tid >> 1;                  // 0..127 (out-row within tile)
    const int hh   = tid & 1;                   // which 32-half of the 64-wide chunk
    const int orow = o0 + r;
    const uint8_t* wrow = g_wb + (size_t)orow * (INSZ / 4);
    // ---- X mapping: 4 threads per batch row, 16 halves each ----
    const int xb = tid >> 2;                    // 0..63
    const int xq = tid & 3;

    // ---- spec-literal fragment coordinates (PTX m16n8k16 tables) ----
    const int g = lid >> 2;                     // groupID
    const int t = lid & 3;                      // threadID_in_group
    const uint32_t a_rel = (uint32_t)(wm * 32 + g) * ASTRIDE + (uint32_t)t * 4;
    const uint32_t b_rel = (uint32_t)(wn * 32 + g) * ASTRIDE + (uint32_t)t * 4;

    // accumulators: [m16 tile i][n8 tile j][4]
    float acc[2][4][4];
#pragma unroll
    for (int i = 0; i < 2; ++i)
#pragma unroll
        for (int j = 0; j < 4; ++j)
#pragma unroll
            for (int q = 0; q < 4; ++q) acc[i][j][q] = 0.0f;

    const uint32_t a_st = (uint32_t)r * ASTRIDE + (uint32_t)hh * 64;   // dequant store base
    const uint32_t x_st = (uint32_t)xb * ASTRIDE + (uint32_t)xq * 32;  // X store base

    for (int c = 0; c < NCHUNK; ++c) {
        const int buf = c & 1;
        const uint32_t baseA = sb + (buf ? SM_A1 : SM_A0);
        const uint32_t baseX = sb + (buf ? SM_X1 : SM_X0);
        const int k0 = kbase + c * KC;

        // ---- dequant 32 weights -> fp16 into SMEM ----
        const uint2 lut = g_lut[orow * NGRP + (k0 >> 6)];
        const uint2 p   = *(const uint2*)(wrow + (k0 >> 2) + hh * 8);
        uint32_t v[16];
#pragma unroll
        for (int j = 0; j < 8; ++j) {
            uint32_t a = (p.x >> (4 * j)) & 0xFu;
            uint32_t u = ((a << 1) & 6u) | (((a >> 1) & 6u) << 8);
            v[j] = __byte_perm(lut.x, lut.y, u * 0x11u + 0x1010u);
        }
#pragma unroll
        for (int j = 0; j < 8; ++j) {
            uint32_t a = (p.y >> (4 * j)) & 0xFu;
            uint32_t u = ((a << 1) & 6u) | (((a >> 1) & 6u) << 8);
            v[8 + j] = __byte_perm(lut.x, lut.y, u * 0x11u + 0x1010u);
        }
#pragma unroll
        for (int i = 0; i < 4; ++i)
            sts128(baseA + a_st + i * 16,
                   v[4 * i], v[4 * i + 1], v[4 * i + 2], v[4 * i + 3]);

        // ---- X tile [64 batch x 64 k] fp16 ----
        const uint4* xs = (const uint4*)(g_xh + (size_t)xb * INSZ + k0 + xq * 16);
        uint4 x0 = xs[0], x1 = xs[1];
        sts128(baseX + x_st,      x0.x, x0.y, x0.z, x0.w);
        sts128(baseX + x_st + 16, x1.x, x1.y, x1.z, x1.w);

        __syncthreads();

        // ---- MMA: D[128(o) x 64(b)] += A[128,64] * X^T ----
#pragma unroll
        for (int s = 0; s < 4; ++s) {
            uint32_t af[2][4], bf[4][2];
#pragma unroll
            for (int i = 0; i < 2; ++i) {
                const uint32_t ab = baseA + a_rel + (uint32_t)i * (16 * ASTRIDE) + (uint32_t)s * 32;
                af[i][0] = lds32(ab);                       // A[g   ][2t  ]
                af[i][1] = lds32(ab + 8 * ASTRIDE);         // A[g+8 ][2t  ]
                af[i][2] = lds32(ab + 16);                  // A[g   ][2t+8]
                af[i][3] = lds32(ab + 8 * ASTRIDE + 16);    // A[g+8 ][2t+8]
            }
#pragma unroll
            for (int j = 0; j < 4; ++j) {
                const uint32_t bb = baseX + b_rel + (uint32_t)j * (8 * ASTRIDE) + (uint32_t)s * 32;
                bf[j][0] = lds32(bb);                       // X[n=g][2t..2t+1]
                bf[j][1] = lds32(bb + 16);                  // X[n=g][2t+8..+9]
            }
#pragma unroll
            for (int i = 0; i < 2; ++i)
#pragma unroll
                for (int j = 0; j < 4; ++j)
                    mma16816(acc[i][j][0], acc[i][j][1], acc[i][j][2], acc[i][j][3],
                             af[i][0], af[i][1], af[i][2], af[i][3],
                             bf[j][0], bf[j][1]);
        }
    }

    // ---- epilogue: write split-K partials ----
    float* pout = g_part + (size_t)ks * (BSZ * OUTSZ);
#pragma unroll
    for (int i = 0; i < 2; ++i) {
        const int r0 = o0 + wm * 32 + i * 16 + g;
        const int r1 = r0 + 8;
#pragma unroll
        for (int j = 0; j < 4; ++j) {
            const int n = wn * 32 + j * 8 + t * 2;
            pout[(size_t)n * OUTSZ + r0]       = acc[i][j][0];
            pout[(size_t)(n + 1) * OUTSZ + r0] = acc[i][j][1];
            pout[(size_t)n * OUTSZ + r1]       = acc[i][j][2];
            pout[(size_t)(n + 1) * OUTSZ + r1] = acc[i][j][3];
        }
    }
}

// ---------------- reduce: sum split-K partials + bias ----------------
__global__ void reduce_kernel(const float* __restrict__ bias, float* __restrict__ out) {
    int idx = blockIdx.x * blockDim.x + threadIdx.x;   // 0 .. BSZ*OUTSZ-1
    const int P = BSZ * OUTSZ;
    out[idx] = (g_part[idx] + g_part[P + idx])
             + (g_part[2 * P + idx] + g_part[3 * P + idx])
             + bias[idx & (OUTSZ - 1)];
}

// ---------------- launch ----------------
extern "C" void kernel_launch(void* const* d_in, const int* in_sizes, int n_in,
                              void* d_out, int out_size) {
    (void)in_sizes; (void)n_in; (void)out_size;
    const float* x      = (const float*)d_in[0];
    const void*  wpk    = d_in[1];
    const float* scales = (const float*)d_in[2];
    const int*   zps    = (const int*)d_in[3];
    const float* bias   = (const float*)d_in[4];
    float*       out    = (float*)d_out;

    cudaFuncSetAttribute(main_kernel, cudaFuncAttributeMaxDynamicSharedMemorySize, SM_TOTAL);

    probe_kernel<<<1, 256>>>((const uint32_t*)wpk);
    repack_kernel<<<WWORDS / 256, 256>>>(wpk);
    prep_kernel<<<(OUTSZ * NGRP) / 256, 256>>>(x, scales, zps);
    main_kernel<<<(OUTSZ / TILE_M) * KSPLIT, NTHREADS, SM_TOTAL>>>();
    reduce_kernel<<<(BSZ * OUTSZ) / 256, 256>>>(bias, out);
}

// round 10
// speedup vs baseline: 1.2289x; 1.2289x over previous
#include <cuda_runtime.h>
#include <cuda_fp16.h>
#include <cstdint>

// ---------------- problem constants ----------------
#define BSZ    64
#define INSZ   8192
#define OUTSZ  8192
#define NGRP   128               // IN / 64
#define TILE_M 128               // output rows per CTA
#define KC     64                // K per chunk = one quant group
#define KSPLIT 4
#define KPER   (INSZ / KSPLIT)   // 2048
#define NCHUNK (KPER / KC)       // 32
#define NTHREADS 256

// padded-row SMEM: 64 k-halves = 128 bytes data + 16 pad = 144 B stride
#define ASTRIDE 144
#define SM_A0  0
#define SM_A1  18432             // 128 * 144
#define SM_X0  36864
#define SM_X1  46080             // + 64 * 144
#define SM_TOTAL 55296

// ---------------- device scratch ----------------
__device__ __half  g_xh[BSZ * INSZ];              // x in fp16
__device__ uint2   g_lut[OUTSZ * NGRP];           // packed fp16 dequant LUT per (row,group)
__device__ float   g_part[KSPLIT * BSZ * OUTSZ];  // split-K partials
__device__ int     g_wfmt;                        // 0=uint8, 1=int32-widened, 2=float32-widened

// ---------------- helpers ----------------
__device__ __forceinline__ uint32_t smem_u32(const void* p) {
    uint32_t a;
    asm("{ .reg .u64 t; cvta.to.shared.u64 t, %1; cvt.u32.u64 %0, t; }" : "=r"(a) : "l"(p));
    return a;
}
__device__ __forceinline__ void sts128(uint32_t addr, uint32_t r0, uint32_t r1,
                                       uint32_t r2, uint32_t r3) {
    asm volatile("st.shared.v4.b32 [%0], {%1, %2, %3, %4};"
                 :: "r"(addr), "r"(r0), "r"(r1), "r"(r2), "r"(r3) : "memory");
}
__device__ __forceinline__ void ldm_x4(uint32_t* r, uint32_t addr) {
    asm volatile("ldmatrix.sync.aligned.m8n8.x4.shared.b16 {%0,%1,%2,%3}, [%4];"
                 : "=r"(r[0]), "=r"(r[1]), "=r"(r[2]), "=r"(r[3]) : "r"(addr));
}
__device__ __forceinline__ void mma16816(float* c,
                                         const uint32_t* a, uint32_t b0, uint32_t b1) {
    asm volatile("mma.sync.aligned.m16n8k16.row.col.f32.f16.f16.f32 "
                 "{%0,%1,%2,%3}, {%4,%5,%6,%7}, {%8,%9}, {%0,%1,%2,%3};"
                 : "+f"(c[0]), "+f"(c[1]), "+f"(c[2]), "+f"(c[3])
                 : "r"(a[0]), "r"(a[1]), "r"(a[2]), "r"(a[3]), "r"(b0), "r"(b1));
}

// ---------------- probe: classify w_packed marshalling format ----------------
__global__ void probe_kernel(const uint32_t* __restrict__ w) {
    __shared__ int cnt_zero, cnt_float;
    if (threadIdx.x == 0) { cnt_zero = 0; cnt_float = 0; }
    __syncthreads();
    int lz = 0, lf = 0;
    for (int i = threadIdx.x; i < 4096; i += blockDim.x) {
        uint32_t tb = w[i] >> 24;
        if (tb == 0) lz++;
        if (tb == 0 || (tb >= 0x3Bu && tb <= 0x43u)) lf++;   // float encodings of 0..255
    }
    atomicAdd(&cnt_zero, lz);
    atomicAdd(&cnt_float, lf);
    __syncthreads();
    if (threadIdx.x == 0) {
        int fmt = 0;                        // packed uint8 (top bytes ~uniform)
        if (cnt_zero == 4096)       fmt = 1; // int32-widened (top byte always 0)
        else if (cnt_float >= 4000) fmt = 2; // float32-widened
        g_wfmt = fmt;
    }
}

// ---------------- prep: x -> fp16, (scale,zp) -> packed fp16 LUT ----------------
__global__ void prep_kernel(const float* __restrict__ x,
                            const float* __restrict__ scales,
                            const int*   __restrict__ zps) {
    int idx = blockIdx.x * blockDim.x + threadIdx.x;   // 0 .. OUTSZ*NGRP-1
    if (idx < OUTSZ * NGRP) {
        float s = scales[idx];
        int   z = zps[idx];
        __half e0 = __float2half((float)(0 - z) * s);
        __half e1 = __float2half((float)(1 - z) * s);
        __half e2 = __float2half((float)(2 - z) * s);
        __half e3 = __float2half((float)(3 - z) * s);
        uint2 l;
        l.x = (uint32_t)__half_as_ushort(e0) | ((uint32_t)__half_as_ushort(e1) << 16);
        l.y = (uint32_t)__half_as_ushort(e2) | ((uint32_t)__half_as_ushort(e3) << 16);
        g_lut[idx] = l;
    }
    if (idx < BSZ * INSZ) {
        g_xh[idx] = __float2half(x[idx]);
    }
}

// ---------------- main: fused (un-marshal + dequant) + mma.sync fp16 GEMM ----------------
__global__ void __launch_bounds__(NTHREADS, 1)
main_kernel(const void* __restrict__ wpk) {
    extern __shared__ char smem[];
    const uint32_t sb  = smem_u32(smem);
    const int tid = threadIdx.x;
    const int wid = tid >> 5;
    const int lid = tid & 31;

    const int ot    = blockIdx.x / KSPLIT;      // OUT tile
    const int ks    = blockIdx.x % KSPLIT;      // K split
    const int o0    = ot * TILE_M;
    const int kbase = ks * KPER;
    const int fmt   = g_wfmt;

    // warp tiling: 4 (m) x 2 (n) warps; warp tile = 32 out-rows x 32 batch-cols
    const int wm = wid >> 1;
    const int wn = wid & 1;

    // ---- dequant mapping: 2 threads per A row, 32 halves each ----
    const int r    = tid >> 1;                  // 0..127 (out-row within tile)
    const int hh   = tid & 1;                   // which 32-half of the 64-wide chunk
    const int orow = o0 + r;
    // ---- X mapping: 4 threads per batch row, 16 halves each ----
    const int xb = tid >> 2;                    // 0..63
    const int xq = tid & 3;

    // ---- ldmatrix source addresses (padded rows, no swizzle: conflict-free) ----
    // A quads: q0 rows0-7@k0, q1 rows8-15@k0, q2 rows0-7@k+8, q3 rows8-15@k+8
    const int aq    = lid >> 3;
    const int arow  = wm * 32 + (lid & 7) + (aq & 1) * 8;
    const uint32_t a_ldrel = (uint32_t)arow * ASTRIDE + (uint32_t)(aq >> 1) * 16;
    // B quads: q0 (n0-7,k0), q1 (n0-7,k+8), q2 (n8-15,k0), q3 (n8-15,k+8)
    const int bn    = wn * 32 + (lid & 7) + ((lid >> 4) & 1) * 8;
    const uint32_t b_ldrel = (uint32_t)bn * ASTRIDE + (uint32_t)((lid >> 3) & 1) * 16;

    // accumulators: [m16 tile i][n8 tile j][4]
    float acc[2][4][4];
#pragma unroll
    for (int i = 0; i < 2; ++i)
#pragma unroll
        for (int j = 0; j < 4; ++j)
#pragma unroll
            for (int q = 0; q < 4; ++q) acc[i][j][q] = 0.0f;

    const uint32_t a_st = (uint32_t)r * ASTRIDE + (uint32_t)hh * 64;   // dequant store base
    const uint32_t x_st = (uint32_t)xb * ASTRIDE + (uint32_t)xq * 32;  // X store base

    for (int c = 0; c < NCHUNK; ++c) {
        const int buf = c & 1;
        const uint32_t baseA = sb + (buf ? SM_A1 : SM_A0);
        const uint32_t baseX = sb + (buf ? SM_X1 : SM_X0);
        const int k0 = kbase + c * KC;

        // ---- un-marshal 8 packed bytes (32 codes) for this thread ----
        const size_t welem = (size_t)orow * (INSZ / 4) + (k0 >> 2) + hh * 8;
        uint2 p;
        if (fmt == 1) {            // int32-widened: 8 words, value-preserving bytes
            const uint32_t* w32 = (const uint32_t*)wpk + welem;
            uint4 va = ((const uint4*)w32)[0];
            uint4 vb = ((const uint4*)w32)[1];
            p.x = (va.x & 0xFFu) | ((va.y & 0xFFu) << 8) | ((va.z & 0xFFu) << 16) | (va.w << 24);
            p.y = (vb.x & 0xFFu) | ((vb.y & 0xFFu) << 8) | ((vb.z & 0xFFu) << 16) | (vb.w << 24);
        } else if (fmt == 2) {     // float32-widened
            const float4* wf = (const float4*)((const float*)wpk + welem);
            float4 va = wf[0], vb = wf[1];
            p.x = ((uint32_t)va.x) | (((uint32_t)va.y) << 8)
                | (((uint32_t)va.z) << 16) | (((uint32_t)va.w) << 24);
            p.y = ((uint32_t)vb.x) | (((uint32_t)vb.y) << 8)
                | (((uint32_t)vb.z) << 16) | (((uint32_t)vb.w) << 24);
        } else {                   // genuine packed uint8
            p = *(const uint2*)((const uint8_t*)wpk + welem);
        }

        // ---- dequant 32 codes -> fp16 into SMEM (PRMT LUT) ----
        const uint2 lut = g_lut[orow * NGRP + (k0 >> 6)];
        uint32_t v[16];
#pragma unroll
        for (int j = 0; j < 8; ++j) {
            uint32_t a = (p.x >> (4 * j)) & 0xFu;
            uint32_t u = ((a << 1) & 6u) | (((a >> 1) & 6u) << 8);
            v[j] = __byte_perm(lut.x, lut.y, u * 0x11u + 0x1010u);
        }
#pragma unroll
        for (int j = 0; j < 8; ++j) {
            uint32_t a = (p.y >> (4 * j)) & 0xFu;
            uint32_t u = ((a << 1) & 6u) | (((a >> 1) & 6u) << 8);
            v[8 + j] = __byte_perm(lut.x, lut.y, u * 0x11u + 0x1010u);
        }
#pragma unroll
        for (int i = 0; i < 4; ++i)
            sts128(baseA + a_st + i * 16,
                   v[4 * i], v[4 * i + 1], v[4 * i + 2], v[4 * i + 3]);

        // ---- X tile [64 batch x 64 k] fp16 ----
        const uint4* xs = (const uint4*)(g_xh + (size_t)xb * INSZ + k0 + xq * 16);
        uint4 x0 = xs[0], x1 = xs[1];
        sts128(baseX + x_st,      x0.x, x0.y, x0.z, x0.w);
        sts128(baseX + x_st + 16, x1.x, x1.y, x1.z, x1.w);

        __syncthreads();

        // ---- MMA: D[128(o) x 64(b)] += A[128,64] * X^T ----
        const uint32_t A0 = baseA + a_ldrel;
        const uint32_t B0 = baseX + b_ldrel;
#pragma unroll
        for (int s = 0; s < 4; ++s) {
            uint32_t a0[4], a1[4], b01[4], b23[4];
            ldm_x4(a0,  A0 + s * 32);                       // m-rows 0-15  of warp tile
            ldm_x4(a1,  A0 + 16 * ASTRIDE + s * 32);        // m-rows 16-31
            ldm_x4(b01, B0 + s * 32);                       // n 0-15 of warp tile
            ldm_x4(b23, B0 + 16 * ASTRIDE + s * 32);        // n 16-31
            mma16816(acc[0][0], a0, b01[0], b01[1]);
            mma16816(acc[0][1], a0, b01[2], b01[3]);
            mma16816(acc[0][2], a0, b23[0], b23[1]);
            mma16816(acc[0][3], a0, b23[2], b23[3]);
            mma16816(acc[1][0], a1, b01[0], b01[1]);
            mma16816(acc[1][1], a1, b01[2], b01[3]);
            mma16816(acc[1][2], a1, b23[0], b23[1]);
            mma16816(acc[1][3], a1, b23[2], b23[3]);
        }
    }

    // ---- epilogue: write split-K partials ----
    // c-frag: {c0,c1}=C[g][2t,2t+1], {c2,c3}=C[g+8][2t,2t+1]
    const int g = lid >> 2;
    const int t = lid & 3;
    float* pout = g_part + (size_t)ks * (BSZ * OUTSZ);
#pragma unroll
    for (int i = 0; i < 2; ++i) {
        const int r0 = o0 + wm * 32 + i * 16 + g;
        const int r1 = r0 + 8;
#pragma unroll
        for (int j = 0; j < 4; ++j) {
            const int n = wn * 32 + j * 8 + t * 2;
            pout[(size_t)n * OUTSZ + r0]       = acc[i][j][0];
            pout[(size_t)(n + 1) * OUTSZ + r0] = acc[i][j][1];
            pout[(size_t)n * OUTSZ + r1]       = acc[i][j][2];
            pout[(size_t)(n + 1) * OUTSZ + r1] = acc[i][j][3];
        }
    }
}

// ---------------- reduce: sum split-K partials + bias ----------------
__global__ void reduce_kernel(const float* __restrict__ bias, float* __restrict__ out) {
    int idx = blockIdx.x * blockDim.x + threadIdx.x;   // 0 .. BSZ*OUTSZ-1
    const int P = BSZ * OUTSZ;
    out[idx] = (g_part[idx] + g_part[P + idx])
             + (g_part[2 * P + idx] + g_part[3 * P + idx])
             + bias[idx & (OUTSZ - 1)];
}

// ---------------- launch ----------------
extern "C" void kernel_launch(void* const* d_in, const int* in_sizes, int n_in,
                              void* d_out, int out_size) {
    (void)in_sizes; (void)n_in; (void)out_size;
    const float* x      = (const float*)d_in[0];
    const void*  wpk    = d_in[1];
    const float* scales = (const float*)d_in[2];
    const int*   zps    = (const int*)d_in[3];
    const float* bias   = (const float*)d_in[4];
    float*       out    = (float*)d_out;

    cudaFuncSetAttribute(main_kernel, cudaFuncAttributeMaxDynamicSharedMemorySize, SM_TOTAL);

    probe_kernel<<<1, 256>>>((const uint32_t*)wpk);
    prep_kernel<<<(OUTSZ * NGRP) / 256, 256>>>(x, scales, zps);
    main_kernel<<<(OUTSZ / TILE_M) * KSPLIT, NTHREADS, SM_TOTAL>>>(wpk);
    reduce_kernel<<<(BSZ * OUTSZ) / 256, 256>>>(bias, out);
}

// round 11
// speedup vs baseline: 1.3006x; 1.0584x over previous
#include <cuda_runtime.h>
#include <cuda_fp16.h>
#include <cstdint>

// ---------------- problem constants ----------------
#define BSZ    64
#define INSZ   8192
#define OUTSZ  8192
#define NGRP   128               // IN / 64
#define TILE_M 128               // output rows per CTA
#define KC     64                // K per chunk = one quant group
#define KSPLIT 4
#define KPER   (INSZ / KSPLIT)   // 2048
#define NCHUNK (KPER / KC)       // 32
#define NTHREADS 256

// padded-row SMEM: 64 k-halves = 128 bytes data + 16 pad = 144 B stride
#define ASTRIDE 144
#define SM_A0  0
#define SM_A1  18432             // 128 * 144
#define SM_X0  36864
#define SM_X1  46080             // + 64 * 144
#define SM_TOTAL 55296

// ---------------- device scratch ----------------
__device__ __half  g_xh[BSZ * INSZ];              // x in fp16
__device__ uint2   g_lut[OUTSZ * NGRP];           // packed fp16 dequant LUT per (row,group)
__device__ float   g_part[KSPLIT * BSZ * OUTSZ];  // split-K partials
__device__ int     g_wfmt;                        // 0=uint8, 1=int32-widened, 2=float32-widened

// ---------------- helpers ----------------
__device__ __forceinline__ uint32_t smem_u32(const void* p) {
    uint32_t a;
    asm("{ .reg .u64 t; cvta.to.shared.u64 t, %1; cvt.u32.u64 %0, t; }" : "=r"(a) : "l"(p));
    return a;
}
__device__ __forceinline__ void sts128(uint32_t addr, uint32_t r0, uint32_t r1,
                                       uint32_t r2, uint32_t r3) {
    asm volatile("st.shared.v4.b32 [%0], {%1, %2, %3, %4};"
                 :: "r"(addr), "r"(r0), "r"(r1), "r"(r2), "r"(r3) : "memory");
}
__device__ __forceinline__ void ldm_x4(uint32_t* r, uint32_t addr) {
    asm volatile("ldmatrix.sync.aligned.m8n8.x4.shared.b16 {%0,%1,%2,%3}, [%4];"
                 : "=r"(r[0]), "=r"(r[1]), "=r"(r[2]), "=r"(r[3]) : "r"(addr));
}
__device__ __forceinline__ void mma16816(float* c,
                                         const uint32_t* a, uint32_t b0, uint32_t b1) {
    asm volatile("mma.sync.aligned.m16n8k16.row.col.f32.f16.f16.f32 "
                 "{%0,%1,%2,%3}, {%4,%5,%6,%7}, {%8,%9}, {%0,%1,%2,%3};"
                 : "+f"(c[0]), "+f"(c[1]), "+f"(c[2]), "+f"(c[3])
                 : "r"(a[0]), "r"(a[1]), "r"(a[2]), "r"(a[3]), "r"(b0), "r"(b1));
}

// raw (possibly widened) weight words for one thread-chunk: 32 codes
struct WRaw { uint4 a, b; };

__device__ __forceinline__ WRaw ldw(const void* wpk, int fmt, size_t welem) {
    WRaw w;
    if (fmt == 0) {                       // genuine packed uint8: 8 bytes
        uint2 t = __ldg((const uint2*)((const uint8_t*)wpk + welem));
        w.a.x = t.x; w.a.y = t.y; w.a.z = 0; w.a.w = 0; w.b = w.a;
    } else {                              // widened: 8 x 32-bit lanes (int or float bits)
        const uint4* p4 = (const uint4*)((const uint32_t*)wpk + welem);
        w.a = __ldg(p4);
        w.b = __ldg(p4 + 1);
    }
    return w;
}
__device__ __forceinline__ uint2 wcvt(const WRaw& w, int fmt) {
    uint2 p;
    if (fmt == 1) {
        p.x = (w.a.x & 0xFFu) | ((w.a.y & 0xFFu) << 8) | ((w.a.z & 0xFFu) << 16) | (w.a.w << 24);
        p.y = (w.b.x & 0xFFu) | ((w.b.y & 0xFFu) << 8) | ((w.b.z & 0xFFu) << 16) | (w.b.w << 24);
    } else if (fmt == 2) {
        p.x = ((uint32_t)__uint_as_float(w.a.x))        | (((uint32_t)__uint_as_float(w.a.y)) << 8)
            | (((uint32_t)__uint_as_float(w.a.z)) << 16) | (((uint32_t)__uint_as_float(w.a.w)) << 24);
        p.y = ((uint32_t)__uint_as_float(w.b.x))        | (((uint32_t)__uint_as_float(w.b.y)) << 8)
            | (((uint32_t)__uint_as_float(w.b.z)) << 16) | (((uint32_t)__uint_as_float(w.b.w)) << 24);
    } else {
        p.x = w.a.x; p.y = w.a.y;
    }
    return p;
}

// ---------------- probe: classify w_packed marshalling format ----------------
__global__ void probe_kernel(const uint32_t* __restrict__ w) {
    __shared__ int cnt_zero, cnt_float;
    if (threadIdx.x == 0) { cnt_zero = 0; cnt_float = 0; }
    __syncthreads();
    int lz = 0, lf = 0;
    for (int i = threadIdx.x; i < 4096; i += blockDim.x) {
        uint32_t tb = w[i] >> 24;
        if (tb == 0) lz++;
        if (tb == 0 || (tb >= 0x3Bu && tb <= 0x43u)) lf++;   // float encodings of 0..255
    }
    atomicAdd(&cnt_zero, lz);
    atomicAdd(&cnt_float, lf);
    __syncthreads();
    if (threadIdx.x == 0) {
        int fmt = 0;                        // packed uint8 (top bytes ~uniform)
        if (cnt_zero == 4096)       fmt = 1; // int32-widened (top byte always 0)
        else if (cnt_float >= 4000) fmt = 2; // float32-widened
        g_wfmt = fmt;
    }
}

// ---------------- prep: x -> fp16, (scale,zp) -> packed fp16 LUT ----------------
__global__ void prep_kernel(const float* __restrict__ x,
                            const float* __restrict__ scales,
                            const int*   __restrict__ zps) {
    int idx = blockIdx.x * blockDim.x + threadIdx.x;   // 0 .. OUTSZ*NGRP-1
    if (idx < OUTSZ * NGRP) {
        float s = scales[idx];
        int   z = zps[idx];
        __half e0 = __float2half((float)(0 - z) * s);
        __half e1 = __float2half((float)(1 - z) * s);
        __half e2 = __float2half((float)(2 - z) * s);
        __half e3 = __float2half((float)(3 - z) * s);
        uint2 l;
        l.x = (uint32_t)__half_as_ushort(e0) | ((uint32_t)__half_as_ushort(e1) << 16);
        l.y = (uint32_t)__half_as_ushort(e2) | ((uint32_t)__half_as_ushort(e3) << 16);
        g_lut[idx] = l;
    }
    if (idx < BSZ * INSZ) {
        g_xh[idx] = __float2half(x[idx]);
    }
}

// ---------------- main: pipelined (un-marshal + dequant) + mma.sync fp16 GEMM ----------------
__global__ void __launch_bounds__(NTHREADS, 1)
main_kernel(const void* __restrict__ wpk) {
    extern __shared__ char smem[];
    const uint32_t sb  = smem_u32(smem);
    const int tid = threadIdx.x;
    const int wid = tid >> 5;
    const int lid = tid & 31;

    const int ot    = blockIdx.x / KSPLIT;      // OUT tile
    const int ks    = blockIdx.x % KSPLIT;      // K split
    const int o0    = ot * TILE_M;
    const int kbase = ks * KPER;
    const int fmt   = g_wfmt;

    // warp tiling: 4 (m) x 2 (n) warps; warp tile = 32 out-rows x 32 batch-cols
    const int wm = wid >> 1;
    const int wn = wid & 1;

    // ---- dequant mapping: 2 threads per A row, 32 halves each ----
    const int r    = tid >> 1;                  // 0..127 (out-row within tile)
    const int hh   = tid & 1;                   // which 32-half of the 64-wide chunk
    const int orow = o0 + r;
    // ---- X mapping: 4 threads per batch row, 16 halves each ----
    const int xb = tid >> 2;                    // 0..63
    const int xq = tid & 3;

    // weight element index base (in units of the marshalled element)
    const size_t wbase = (size_t)orow * (INSZ / 4) + (kbase >> 2) + hh * 8;
    const __half* xsrc = g_xh + (size_t)xb * INSZ + kbase + xq * 16;

    // ---- ldmatrix source addresses (padded rows, no swizzle: conflict-free) ----
    const int aq    = lid >> 3;
    const int arow  = wm * 32 + (lid & 7) + (aq & 1) * 8;
    const uint32_t a_ldrel = (uint32_t)arow * ASTRIDE + (uint32_t)(aq >> 1) * 16;
    const int bn    = wn * 32 + (lid & 7) + ((lid >> 4) & 1) * 8;
    const uint32_t b_ldrel = (uint32_t)bn * ASTRIDE + (uint32_t)((lid >> 3) & 1) * 16;

    // accumulators: [m16 tile i][n8 tile j][4]
    float acc[2][4][4];
#pragma unroll
    for (int i = 0; i < 2; ++i)
#pragma unroll
        for (int j = 0; j < 4; ++j)
#pragma unroll
            for (int q = 0; q < 4; ++q) acc[i][j][q] = 0.0f;

    const uint32_t a_st = (uint32_t)r * ASTRIDE + (uint32_t)hh * 64;   // dequant store base
    const uint32_t x_st = (uint32_t)xb * ASTRIDE + (uint32_t)xq * 32;  // X store base

    // ---- prologue: prefetch chunk 0 ----
    WRaw  wr  = ldw(wpk, fmt, wbase);
    uint4 xr0 = __ldg((const uint4*)xsrc);
    uint4 xr1 = __ldg((const uint4*)xsrc + 1);

    for (int c = 0; c < NCHUNK; ++c) {
        const int buf = c & 1;
        const uint32_t baseA = sb + (buf ? SM_A1 : SM_A0);
        const uint32_t baseX = sb + (buf ? SM_X1 : SM_X0);
        const int k0 = kbase + c * KC;

        // ---- dequant 32 codes (from prefetched regs) -> fp16 into SMEM ----
        const uint2 p   = wcvt(wr, fmt);
        const uint2 lut = g_lut[orow * NGRP + (k0 >> 6)];
        uint32_t v[16];
#pragma unroll
        for (int j = 0; j < 8; ++j) {
            uint32_t a = (p.x >> (4 * j)) & 0xFu;
            uint32_t u = ((a << 1) & 6u) | (((a >> 1) & 6u) << 8);
            v[j] = __byte_perm(lut.x, lut.y, u * 0x11u + 0x1010u);
        }
#pragma unroll
        for (int j = 0; j < 8; ++j) {
            uint32_t a = (p.y >> (4 * j)) & 0xFu;
            uint32_t u = ((a << 1) & 6u) | (((a >> 1) & 6u) << 8);
            v[8 + j] = __byte_perm(lut.x, lut.y, u * 0x11u + 0x1010u);
        }
#pragma unroll
        for (int i = 0; i < 4; ++i)
            sts128(baseA + a_st + i * 16,
                   v[4 * i], v[4 * i + 1], v[4 * i + 2], v[4 * i + 3]);

        // ---- X tile from prefetched regs ----
        sts128(baseX + x_st,      xr0.x, xr0.y, xr0.z, xr0.w);
        sts128(baseX + x_st + 16, xr1.x, xr1.y, xr1.z, xr1.w);

        // ---- prefetch chunk c+1 (latency hidden under the MMA below) ----
        if (c + 1 < NCHUNK) {
            wr  = ldw(wpk, fmt, wbase + (size_t)(c + 1) * 16);
            xr0 = __ldg((const uint4*)(xsrc + (c + 1) * KC));
            xr1 = __ldg((const uint4*)(xsrc + (c + 1) * KC) + 1);
        }

        __syncthreads();

        // ---- MMA: D[128(o) x 64(b)] += A[128,64] * X^T ----
        const uint32_t A0 = baseA + a_ldrel;
        const uint32_t B0 = baseX + b_ldrel;
#pragma unroll
        for (int s = 0; s < 4; ++s) {
            uint32_t a0[4], a1[4], b01[4], b23[4];
            ldm_x4(a0,  A0 + s * 32);                       // m-rows 0-15  of warp tile
            ldm_x4(a1,  A0 + 16 * ASTRIDE + s * 32);        // m-rows 16-31
            ldm_x4(b01, B0 + s * 32);                       // n 0-15 of warp tile
            ldm_x4(b23, B0 + 16 * ASTRIDE + s * 32);        // n 16-31
            mma16816(acc[0][0], a0, b01[0], b01[1]);
            mma16816(acc[0][1], a0, b01[2], b01[3]);
            mma16816(acc[0][2], a0, b23[0], b23[1]);
            mma16816(acc[0][3], a0, b23[2], b23[3]);
            mma16816(acc[1][0], a1, b01[0], b01[1]);
            mma16816(acc[1][1], a1, b01[2], b01[3]);
            mma16816(acc[1][2], a1, b23[0], b23[1]);
            mma16816(acc[1][3], a1, b23[2], b23[3]);
        }
    }

    // ---- epilogue: write split-K partials ----
    const int g = lid >> 2;
    const int t = lid & 3;
    float* pout = g_part + (size_t)ks * (BSZ * OUTSZ);
#pragma unroll
    for (int i = 0; i < 2; ++i) {
        const int r0 = o0 + wm * 32 + i * 16 + g;
        const int r1 = r0 + 8;
#pragma unroll
        for (int j = 0; j < 4; ++j) {
            const int n = wn * 32 + j * 8 + t * 2;
            pout[(size_t)n * OUTSZ + r0]       = acc[i][j][0];
            pout[(size_t)(n + 1) * OUTSZ + r0] = acc[i][j][1];
            pout[(size_t)n * OUTSZ + r1]       = acc[i][j][2];
            pout[(size_t)(n + 1) * OUTSZ + r1] = acc[i][j][3];
        }
    }
}

// ---------------- reduce: sum split-K partials + bias (vectorized) ----------------
__global__ void reduce_kernel(const float* __restrict__ bias, float* __restrict__ out) {
    const int idx = (blockIdx.x * blockDim.x + threadIdx.x) * 4;   // element index
    const int P = BSZ * OUTSZ;
    const float4 p0 = *(const float4*)(g_part + idx);
    const float4 p1 = *(const float4*)(g_part + P + idx);
    const float4 p2 = *(const float4*)(g_part + 2 * P + idx);
    const float4 p3 = *(const float4*)(g_part + 3 * P + idx);
    const float4 bb = __ldg((const float4*)(bias + (idx & (OUTSZ - 1))));
    float4 o;
    o.x = (p0.x + p1.x) + (p2.x + p3.x) + bb.x;
    o.y = (p0.y + p1.y) + (p2.y + p3.y) + bb.y;
    o.z = (p0.z + p1.z) + (p2.z + p3.z) + bb.z;
    o.w = (p0.w + p1.w) + (p2.w + p3.w) + bb.w;
    *(float4*)(out + idx) = o;
}

// ---------------- launch ----------------
extern "C" void kernel_launch(void* const* d_in, const int* in_sizes, int n_in,
                              void* d_out, int out_size) {
    (void)in_sizes; (void)n_in; (void)out_size;
    const float* x      = (const float*)d_in[0];
    const void*  wpk    = d_in[1];
    const float* scales = (const float*)d_in[2];
    const int*   zps    = (const int*)d_in[3];
    const float* bias   = (const float*)d_in[4];
    float*       out    = (float*)d_out;

    cudaFuncSetAttribute(main_kernel, cudaFuncAttributeMaxDynamicSharedMemorySize, SM_TOTAL);

    probe_kernel<<<1, 256>>>((const uint32_t*)wpk);
    prep_kernel<<<(OUTSZ * NGRP) / 256, 256>>>(x, scales, zps);
    main_kernel<<<(OUTSZ / TILE_M) * KSPLIT, NTHREADS, SM_TOTAL>>>(wpk);
    reduce_kernel<<<(BSZ * OUTSZ) / 1024, 256>>>(bias, out);
}

// round 14
// speedup vs baseline: 1.3337x; 1.0254x over previous
#include <cuda_runtime.h>
#include <cuda_fp16.h>
#include <cstdint>

// ---------------- problem constants ----------------
#define BSZ    64
#define INSZ   8192
#define OUTSZ  8192
#define NGRP   128               // IN / 64
#define TILE_M 128               // output rows per CTA
#define KC     64                // K per chunk = one quant group
#define KSPLIT 4
#define KPER   (INSZ / KSPLIT)   // 2048
#define NCHUNK (KPER / KC)       // 32
#define NTHREADS 256

// padded-row SMEM: 64 k-halves = 128 bytes data + 16 pad = 144 B stride
#define ASTRIDE 144
#define SM_A0  0
#define SM_A1  18432             // 128 * 144
#define SM_X0  36864
#define SM_X1  46080             // + 64 * 144
#define SM_TOTAL 55296

// ---------------- device scratch ----------------
__device__ __half  g_xh[BSZ * INSZ];              // x in fp16
__device__ uint2   g_lut[OUTSZ * NGRP];           // packed fp16 dequant LUT per (row,group)
__device__ float   g_part[KSPLIT * BSZ * OUTSZ];  // split-K partials

// ---------------- helpers ----------------
__device__ __forceinline__ uint32_t smem_u32(const void* p) {
    uint32_t a;
    asm("{ .reg .u64 t; cvta.to.shared.u64 t, %1; cvt.u32.u64 %0, t; }" : "=r"(a) : "l"(p));
    return a;
}
__device__ __forceinline__ void sts128(uint32_t addr, uint32_t r0, uint32_t r1,
                                       uint32_t r2, uint32_t r3) {
    asm volatile("st.shared.v4.b32 [%0], {%1, %2, %3, %4};"
                 :: "r"(addr), "r"(r0), "r"(r1), "r"(r2), "r"(r3) : "memory");
}
__device__ __forceinline__ void ldm_x4(uint32_t* r, uint32_t addr) {
    asm volatile("ldmatrix.sync.aligned.m8n8.x4.shared.b16 {%0,%1,%2,%3}, [%4];"
                 : "=r"(r[0]), "=r"(r[1]), "=r"(r[2]), "=r"(r[3]) : "r"(addr));
}
__device__ __forceinline__ void mma16816(float* c,
                                         const uint32_t* a, uint32_t b0, uint32_t b1) {
    asm volatile("mma.sync.aligned.m16n8k16.row.col.f32.f16.f16.f32 "
                 "{%0,%1,%2,%3}, {%4,%5,%6,%7}, {%8,%9}, {%0,%1,%2,%3};"
                 : "+f"(c[0]), "+f"(c[1]), "+f"(c[2]), "+f"(c[3])
                 : "r"(a[0]), "r"(a[1]), "r"(a[2]), "r"(a[3]), "r"(b0), "r"(b1));
}

// raw (possibly widened) weight words for one thread-chunk: 32 codes
struct WRaw { uint4 a, b; };

__device__ __forceinline__ WRaw ldw(const void* wpk, int fmt, size_t welem) {
    WRaw w;
    if (fmt == 0) {                       // genuine packed uint8: 8 bytes
        uint2 t = __ldg((const uint2*)((const uint8_t*)wpk + welem));
        w.a.x = t.x; w.a.y = t.y; w.a.z = 0; w.a.w = 0; w.b = w.a;
    } else {                              // widened: 8 x 32-bit lanes (int or float bits)
        const uint4* p4 = (const uint4*)((const uint32_t*)wpk + welem);
        w.a = __ldg(p4);
        w.b = __ldg(p4 + 1);
    }
    return w;
}
__device__ __forceinline__ uint2 wcvt(const WRaw& w, int fmt) {
    uint2 p;
    if (fmt == 1) {
        p.x = (w.a.x & 0xFFu) | ((w.a.y & 0xFFu) << 8) | ((w.a.z & 0xFFu) << 16) | (w.a.w << 24);
        p.y = (w.b.x & 0xFFu) | ((w.b.y & 0xFFu) << 8) | ((w.b.z & 0xFFu) << 16) | (w.b.w << 24);
    } else if (fmt == 2) {
        p.x = ((uint32_t)__uint_as_float(w.a.x))        | (((uint32_t)__uint_as_float(w.a.y)) << 8)
            | (((uint32_t)__uint_as_float(w.a.z)) << 16) | (((uint32_t)__uint_as_float(w.a.w)) << 24);
        p.y = ((uint32_t)__uint_as_float(w.b.x))        | (((uint32_t)__uint_as_float(w.b.y)) << 8)
            | (((uint32_t)__uint_as_float(w.b.z)) << 16) | (((uint32_t)__uint_as_float(w.b.w)) << 24);
    } else {
        p.x = w.a.x; p.y = w.a.y;
    }
    return p;
}

// ---------------- prep: x -> fp16, (scale,zp) -> packed fp16 LUT (vectorized) ----------------
__global__ void prep_kernel(const float* __restrict__ x,
                            const float* __restrict__ scales,
                            const int*   __restrict__ zps) {
    const int tid = blockIdx.x * blockDim.x + threadIdx.x;   // 0 .. OUTSZ*NGRP/2 - 1
    // LUT: 2 entries per thread
    {
        const int i2 = tid * 2;
        const float2 s2 = __ldg((const float2*)(scales + i2));
        const int2   z2 = __ldg((const int2*)(zps + i2));
        uint2 l0, l1;
        {
            float s = s2.x; int z = z2.x;
            l0.x = (uint32_t)__half_as_ushort(__float2half((0 - z) * s))
                 | ((uint32_t)__half_as_ushort(__float2half((1 - z) * s)) << 16);
            l0.y = (uint32_t)__half_as_ushort(__float2half((2 - z) * s))
                 | ((uint32_t)__half_as_ushort(__float2half((3 - z) * s)) << 16);
        }
        {
            float s = s2.y; int z = z2.y;
            l1.x = (uint32_t)__half_as_ushort(__float2half((0 - z) * s))
                 | ((uint32_t)__half_as_ushort(__float2half((1 - z) * s)) << 16);
            l1.y = (uint32_t)__half_as_ushort(__float2half((2 - z) * s))
                 | ((uint32_t)__half_as_ushort(__float2half((3 - z) * s)) << 16);
        }
        uint4 pkt; pkt.x = l0.x; pkt.y = l0.y; pkt.z = l1.x; pkt.w = l1.y;
        *(uint4*)(g_lut + i2) = pkt;
    }
    // x: 8 floats -> 8 halves per thread (first 64K threads)
    if (tid < (BSZ * INSZ) / 8) {
        const float4 f0 = __ldg((const float4*)(x + tid * 8));
        const float4 f1 = __ldg((const float4*)(x + tid * 8) + 1);
        uint4 h;
        h.x = (uint32_t)__half_as_ushort(__float2half(f0.x))
            | ((uint32_t)__half_as_ushort(__float2half(f0.y)) << 16);
        h.y = (uint32_t)__half_as_ushort(__float2half(f0.z))
            | ((uint32_t)__half_as_ushort(__float2half(f0.w)) << 16);
        h.z = (uint32_t)__half_as_ushort(__float2half(f1.x))
            | ((uint32_t)__half_as_ushort(__float2half(f1.y)) << 16);
        h.w = (uint32_t)__half_as_ushort(__float2half(f1.z))
            | ((uint32_t)__half_as_ushort(__float2half(f1.w)) << 16);
        *(uint4*)(g_xh + tid * 8) = h;
    }
}

// ---------------- main: overlapped (un-marshal + dequant) + mma.sync fp16 GEMM ----------------
__global__ void __launch_bounds__(NTHREADS, 1)
main_kernel(const void* __restrict__ wpk) {
    extern __shared__ char smem[];
    const uint32_t sb  = smem_u32(smem);
    const int tid = threadIdx.x;
    const int wid = tid >> 5;
    const int lid = tid & 31;

    // ---- inline marshalling-format detection (replaces probe kernel) ----
    int fmt;
    {
        const uint32_t wv = ((const uint32_t*)wpk)[tid];
        const uint32_t tb = wv >> 24;
        const int allz = __syncthreads_and(tb == 0);
        const int allf = __syncthreads_and(tb == 0 || (tb >= 0x3Bu && tb <= 0x43u));
        fmt = allz ? 1 : (allf ? 2 : 0);
    }

    const int ot    = blockIdx.x / KSPLIT;      // OUT tile
    const int ks    = blockIdx.x % KSPLIT;      // K split
    const int o0    = ot * TILE_M;
    const int kbase = ks * KPER;

    // warp tiling: 4 (m) x 2 (n) warps; warp tile = 32 out-rows x 32 batch-cols
    const int wm = wid >> 1;
    const int wn = wid & 1;

    // ---- dequant mapping: 2 threads per A row, 32 halves each ----
    const int r    = tid >> 1;                  // 0..127 (out-row within tile)
    const int hh   = tid & 1;                   // which 32-half of the 64-wide chunk
    const int orow = o0 + r;
    // ---- X mapping: 4 threads per batch row, 16 halves each ----
    const int xb = tid >> 2;                    // 0..63
    const int xq = tid & 3;

    const size_t wbase = (size_t)orow * (INSZ / 4) + (kbase >> 2) + hh * 8;
    const __half* xsrc = g_xh + (size_t)xb * INSZ + kbase + xq * 16;

    // ---- ldmatrix source addresses (padded rows, no swizzle: conflict-free) ----
    const int aq    = lid >> 3;
    const int arow  = wm * 32 + (lid & 7) + (aq & 1) * 8;
    const uint32_t a_ldrel = (uint32_t)arow * ASTRIDE + (uint32_t)(aq >> 1) * 16;
    const int bn    = wn * 32 + (lid & 7) + ((lid >> 4) & 1) * 8;
    const uint32_t b_ldrel = (uint32_t)bn * ASTRIDE + (uint32_t)((lid >> 3) & 1) * 16;

    float acc[2][4][4];
#pragma unroll
    for (int i = 0; i < 2; ++i)
#pragma unroll
        for (int j = 0; j < 4; ++j)
#pragma unroll
            for (int q = 0; q < 4; ++q) acc[i][j][q] = 0.0f;

    const uint32_t a_st = (uint32_t)r * ASTRIDE + (uint32_t)hh * 64;
    const uint32_t x_st = (uint32_t)xb * ASTRIDE + (uint32_t)xq * 32;

    // ---- prologue: load chunk 0, dequant into buf0, prefetch chunk 1 ----
    WRaw  wr  = ldw(wpk, fmt, wbase);
    uint4 xr0 = __ldg((const uint4*)xsrc);
    uint4 xr1 = __ldg((const uint4*)xsrc + 1);
    {
        const uint2 p   = wcvt(wr, fmt);
        const uint2 lut = g_lut[orow * NGRP + (kbase >> 6)];
        uint32_t v[16];
#pragma unroll
        for (int j = 0; j < 8; ++j) {
            uint32_t a = (p.x >> (4 * j)) & 0xFu;
            uint32_t u = ((a << 1) & 6u) | (((a >> 1) & 6u) << 8);
            v[j] = __byte_perm(lut.x, lut.y, u * 0x11u + 0x1010u);
        }
#pragma unroll
        for (int j = 0; j < 8; ++j) {
            uint32_t a = (p.y >> (4 * j)) & 0xFu;
            uint32_t u = ((a << 1) & 6u) | (((a >> 1) & 6u) << 8);
            v[8 + j] = __byte_perm(lut.x, lut.y, u * 0x11u + 0x1010u);
        }
#pragma unroll
        for (int i = 0; i < 4; ++i)
            sts128(sb + SM_A0 + a_st + i * 16,
                   v[4 * i], v[4 * i + 1], v[4 * i + 2], v[4 * i + 3]);
        sts128(sb + SM_X0 + x_st,      xr0.x, xr0.y, xr0.z, xr0.w);
        sts128(sb + SM_X0 + x_st + 16, xr1.x, xr1.y, xr1.z, xr1.w);
    }
    if (NCHUNK > 1) {
        wr  = ldw(wpk, fmt, wbase + 16);
        xr0 = __ldg((const uint4*)(xsrc + KC));
        xr1 = __ldg((const uint4*)(xsrc + KC) + 1);
    }
    __syncthreads();

    // ---- mainloop: ONE barrier per chunk; MMA(c) and dequant(c+1) unordered within ----
    for (int c = 0; c < NCHUNK; ++c) {
        const int buf = c & 1;
        const uint32_t baseA = sb + (buf ? SM_A1 : SM_A0);
        const uint32_t baseX = sb + (buf ? SM_X1 : SM_X0);

        // MMA on chunk c (inputs ready since last barrier)
        const uint32_t A0 = baseA + a_ldrel;
        const uint32_t B0 = baseX + b_ldrel;
#pragma unroll
        for (int s = 0; s < 4; ++s) {
            uint32_t a0[4], a1[4], b01[4], b23[4];
            ldm_x4(a0,  A0 + s * 32);
            ldm_x4(a1,  A0 + 16 * ASTRIDE + s * 32);
            ldm_x4(b01, B0 + s * 32);
            ldm_x4(b23, B0 + 16 * ASTRIDE + s * 32);
            mma16816(acc[0][0], a0, b01[0], b01[1]);
            mma16816(acc[0][1], a0, b01[2], b01[3]);
            mma16816(acc[0][2], a0, b23[0], b23[1]);
            mma16816(acc[0][3], a0, b23[2], b23[3]);
            mma16816(acc[1][0], a1, b01[0], b01[1]);
            mma16816(acc[1][1], a1, b01[2], b01[3]);
            mma16816(acc[1][2], a1, b23[0], b23[1]);
            mma16816(acc[1][3], a1, b23[2], b23[3]);
        }

        // produce chunk c+1 into the opposite buffer (safe: its readers retired
        // at the previous barrier; current MMA reads the other buffer)
        if (c + 1 < NCHUNK) {
            const uint32_t baseA2 = sb + (buf ? SM_A0 : SM_A1);
            const uint32_t baseX2 = sb + (buf ? SM_X0 : SM_X1);
            const int k1 = kbase + (c + 1) * KC;
            const uint2 p   = wcvt(wr, fmt);
            const uint2 lut = g_lut[orow * NGRP + (k1 >> 6)];
            uint32_t v[16];
#pragma unroll
            for (int j = 0; j < 8; ++j) {
                uint32_t a = (p.x >> (4 * j)) & 0xFu;
                uint32_t u = ((a << 1) & 6u) | (((a >> 1) & 6u) << 8);
                v[j] = __byte_perm(lut.x, lut.y, u * 0x11u + 0x1010u);
            }
#pragma unroll
            for (int j = 0; j < 8; ++j) {
                uint32_t a = (p.y >> (4 * j)) & 0xFu;
                uint32_t u = ((a << 1) & 6u) | (((a >> 1) & 6u) << 8);
                v[8 + j] = __byte_perm(lut.x, lut.y, u * 0x11u + 0x1010u);
            }
#pragma unroll
            for (int i = 0; i < 4; ++i)
                sts128(baseA2 + a_st + i * 16,
                       v[4 * i], v[4 * i + 1], v[4 * i + 2], v[4 * i + 3]);
            sts128(baseX2 + x_st,      xr0.x, xr0.y, xr0.z, xr0.w);
            sts128(baseX2 + x_st + 16, xr1.x, xr1.y, xr1.z, xr1.w);

            if (c + 2 < NCHUNK) {   // prefetch chunk c+2 (hidden under next MMA)
                wr  = ldw(wpk, fmt, wbase + (size_t)(c + 2) * 16);
                xr0 = __ldg((const uint4*)(xsrc + (c + 2) * KC));
                xr1 = __ldg((const uint4*)(xsrc + (c + 2) * KC) + 1);
            }
        }
        __syncthreads();
    }

    // ---- epilogue: write split-K partials ----
    const int g = lid >> 2;
    const int t = lid & 3;
    float* pout = g_part + (size_t)ks * (BSZ * OUTSZ);
#pragma unroll
    for (int i = 0; i < 2; ++i) {
        const int r0 = o0 + wm * 32 + i * 16 + g;
        const int r1 = r0 + 8;
#pragma unroll
        for (int j = 0; j < 4; ++j) {
            const int n = wn * 32 + j * 8 + t * 2;
            pout[(size_t)n * OUTSZ + r0]       = acc[i][j][0];
            pout[(size_t)(n + 1) * OUTSZ + r0] = acc[i][j][1];
            pout[(size_t)n * OUTSZ + r1]       = acc[i][j][2];
            pout[(size_t)(n + 1) * OUTSZ + r1] = acc[i][j][3];
        }
    }
}

// ---------------- reduce: sum split-K partials + bias (8 elem / thread) ----------------
__global__ void reduce_kernel(const float* __restrict__ bias, float* __restrict__ out) {
    const int base = (blockIdx.x * blockDim.x + threadIdx.x) * 8;
    const int P = BSZ * OUTSZ;
#pragma unroll
    for (int h = 0; h < 2; ++h) {
        const int idx = base + h * 4;
        const float4 p0 = *(const float4*)(g_part + idx);
        const float4 p1 = *(const float4*)(g_part + P + idx);
        const float4 p2 = *(const float4*)(g_part + 2 * P + idx);
        const float4 p3 = *(const float4*)(g_part + 3 * P + idx);
        const float4 bb = __ldg((const float4*)(bias + (idx & (OUTSZ - 1))));
        float4 o;
        o.x = (p0.x + p1.x) + (p2.x + p3.x) + bb.x;
        o.y = (p0.y + p1.y) + (p2.y + p3.y) + bb.y;
        o.z = (p0.z + p1.z) + (p2.z + p3.z) + bb.z;
        o.w = (p0.w + p1.w) + (p2.w + p3.w) + bb.w;
        *(float4*)(out + idx) = o;
    }
}

// ---------------- launch ----------------
extern "C" void kernel_launch(void* const* d_in, const int* in_sizes, int n_in,
                              void* d_out, int out_size) {
    (void)in_sizes; (void)n_in; (void)out_size;
    const float* x      = (const float*)d_in[0];
    const void*  wpk    = d_in[1];
    const float* scales = (const float*)d_in[2];
    const int*   zps    = (const int*)d_in[3];
    const float* bias   = (const float*)d_in[4];
    float*       out    = (float*)d_out;

    cudaFuncSetAttribute(main_kernel, cudaFuncAttributeMaxDynamicSharedMemorySize, SM_TOTAL);

    prep_kernel<<<(OUTSZ * NGRP / 2) / 256, 256>>>(x, scales, zps);
    main_kernel<<<(OUTSZ / TILE_M) * KSPLIT, NTHREADS, SM_TOTAL>>>(wpk);
    reduce_kernel<<<(BSZ * OUTSZ) / 2048, 256>>>(bias, out);
}